// round 6
// baseline (speedup 1.0000x reference)
#include <cuda_runtime.h>
#include <cstddef>

#define NPTS 1024
#define DIM  128
#define FULLMASK 0xffffffffu
#define CAP 256

// ---- per-point scratch ----
__device__ float g_x2[NPTS];
__device__ float g_E[NPTS];   // exp(-(left_i + b))
__device__ float g_F[NPTS];   // exp(-right_j)

__device__ __forceinline__ float warp_sum(float v) {
#pragma unroll
    for (int o = 16; o > 0; o >>= 1) v += __shfl_xor_sync(FULLMASK, v, o);
    return v;
}

// atanh(min(s,1-1e-7)) via fast log; s >= 0
__device__ __forceinline__ float fast_atanh(float s) {
    s = fminf(s, 1.0f - 1e-7f);
    return 0.5f * __logf(__fdividef(1.0f + s, 1.0f - s));
}

// ---------------------------------------------------------------------------
// Kernel 1: per-point scalars. 128 blocks x 256 threads, warp per point.
// ---------------------------------------------------------------------------
__global__ void __launch_bounds__(256) k_pre(
    const float* __restrict__ x, const float* __restrict__ w,
    const float* __restrict__ bptr)
{
    int warp = threadIdx.x >> 5, lane = threadIdx.x & 31;
    int i = blockIdx.x * 8 + warp;
    float4 v  = *(const float4*)&x[i * DIM + lane * 4];
    float4 wl = *(const float4*)&w[lane * 4];
    float4 wr = *(const float4*)&w[DIM + lane * 4];
    float p2 = v.x * v.x + v.y * v.y + v.z * v.z + v.w * v.w;
    float d1 = v.x * wl.x + v.y * wl.y + v.z * wl.z + v.w * wl.w;
    float d2 = v.x * wr.x + v.y * wr.y + v.z * wr.z + v.w * wr.w;
    p2 = warp_sum(p2); d1 = warp_sum(d1); d2 = warp_sum(d2);
    if (lane == 0) {
        float pn  = sqrtf(fmaxf(p2, 1e-15f));
        float fac = fast_atanh(pn) / pn;          // logmap0 scalar
        g_x2[i] = p2;
        g_E[i]  = __expf(-(fac * d1 + bptr[0]));
        g_F[i]  = __expf(-(fac * d2));
    }
}

// ---------------------------------------------------------------------------
// Kernel 2: fused sparse aggregation + expmap. Block (128 thr) per row i.
// step2: quad-per-pair, interleaved 64B slices, single FMA chain (dot only);
// per-point scalars come from g_x2/g_F; sigmoid = av/(1+E_i*F_j).
// ---------------------------------------------------------------------------
__global__ void __launch_bounds__(128, 8) k_fused(
    const float* __restrict__ x, const float* __restrict__ adj,
    float* __restrict__ out)
{
    __shared__ __align__(16) float s_xi[DIM];
    __shared__ int   s_idx[CAP];
    __shared__ float s_val[CAP];
    __shared__ float s_wb[CAP];
    __shared__ __align__(16) float s_u[4][DIM];
    __shared__ float s_red[4];
    __shared__ int   s_wcnt[4];

    const int i    = blockIdx.x;
    const int t    = threadIdx.x;          // 0..127
    const int warp = t >> 5, lane = t & 31;

    // ---- step 0: stage x_i; per-row scalars from precompute ----
    s_xi[t] = x[i * DIM + t];
    const float x2i  = g_x2[i];
    const float Ei   = g_E[i];
    const float omi  = 1.0f - x2i;
    const float omci = fmaxf(omi, 1e-15f);

    // ---- step 1: compaction (warp w scans 256 entries; vals re-read) ----
    const float* arow = adj + (size_t)i * NPTS + warp * 256;
    unsigned masks[8];
    int mycnt = 0;
#pragma unroll
    for (int c = 0; c < 8; c++) {
        float v = arow[c * 32 + lane];
        unsigned m = __ballot_sync(FULLMASK, v != 0.0f);
        masks[c] = m;
        mycnt += __popc(m);
    }
    if (lane == 0) s_wcnt[warp] = mycnt;
    __syncthreads();
    int run = 0;
#pragma unroll
    for (int w = 0; w < 4; w++) if (w < warp) run += s_wcnt[w];
#pragma unroll
    for (int c = 0; c < 8; c++) {
        unsigned m = masks[c];
        if (m & (1u << lane)) {
            int pos = run + __popc(m & ((1u << lane) - 1));
            if (pos < CAP) {
                s_idx[pos] = warp * 256 + c * 32 + lane;
                s_val[pos] = arow[c * 32 + lane];   // L1 hit
            }
        }
        run += __popc(m);
    }
    const int cnt = min(s_wcnt[0] + s_wcnt[1] + s_wcnt[2] + s_wcnt[3], CAP);
    __syncthreads();

    // ---- step 2: quad-per-pair dot + scalar chain (32 pairs per sweep) ----
    const int slice = lane & 3;
    float4 xir[8];
#pragma unroll
    for (int m = 0; m < 8; m++) xir[m] = ((const float4*)s_xi)[m * 4 + slice];

    float wa_lane = 0.0f;
    for (int kb = 0; kb < cnt; kb += 32) {
        int  k   = kb + warp * 8 + (lane >> 2);
        bool act = k < cnt;
        int  j   = act ? s_idx[k] : i;
        float av = act ? s_val[k] : 0.0f;
        const float4* xj4 = (const float4*)(x + j * DIM);
        float d = 0.f;
#pragma unroll
        for (int m = 0; m < 8; m++) {
            float4 b  = xj4[m * 4 + slice];            // quad covers 64B/m
            float4 aa = xir[m];
            d += aa.x * b.x + aa.y * b.y + aa.z * b.z + aa.w * b.w;
        }
        d += __shfl_xor_sync(FULLMASK, d, 1);
        d += __shfl_xor_sync(FULLMASK, d, 2);

        float x2j = g_x2[j];
        float Fj  = g_F[j];
        // attention: adj * sigmoid(left+right+b) = av / (1 + Ei*Fj)
        float sig = __fdividef(av, 1.0f + Ei * Fj);
        // pairwise logmap scalar chain
        float P   = 1.0f - 2.0f * d;
        float A   = P + x2j;                             // coeff of -x_i
        float den = fmaxf(P + x2i * x2j, 1e-15f);        // mobius denom
        float Q   = x2i * A * A - 2.0f * A * omi * d + x2j * omi * omi;
        Q = fmaxf(Q, 1e-15f * den * den);                // sn2 clamp * den^2
        float rq  = rsqrtf(Q);
        float sq  = Q * rq;                              // sqrt(Q)
        float dm  = fmaxf(den - sq, 1e-7f * den);        // atanh clip
        float ath = 0.5f * __logf(__fdividef(den + sq, dm));
        float wgt = sig * omci * ath * rq;
        if (slice == 0) {
            wa_lane += wgt * A;
            if (act) s_wb[k] = wgt * omi;
        }
    }
    wa_lane = warp_sum(wa_lane);
    if (lane == 0) s_red[warp] = wa_lane;
    __syncthreads();

    // ---- step 3: dim-per-lane coalesced aggregation ----
    float4 u = {0.f, 0.f, 0.f, 0.f};
    for (int k = warp; k < cnt; k += 4) {
        float wb = s_wb[k];
        float4 b = *(const float4*)(x + s_idx[k] * DIM + 4 * lane);
        u.x += wb * b.x; u.y += wb * b.y; u.z += wb * b.z; u.w += wb * b.w;
    }
    ((float4*)s_u[warp])[lane] = u;
    __syncthreads();

    // ---- step 4: expmap epilogue (warp 0, float4 per lane covers D=128) ----
    if (warp == 0) {
        float4 u0 = ((const float4*)s_u[0])[lane];
        float4 u1 = ((const float4*)s_u[1])[lane];
        float4 u2 = ((const float4*)s_u[2])[lane];
        float4 u3 = ((const float4*)s_u[3])[lane];
        float  wa = s_red[0] + s_red[1] + s_red[2] + s_red[3];
        float4 xi = ((const float4*)s_xi)[lane];
        float4 uu;
        uu.x = (u0.x + u1.x) + (u2.x + u3.x) - wa * xi.x;
        uu.y = (u0.y + u1.y) + (u2.y + u3.y) - wa * xi.y;
        uu.z = (u0.z + u1.z) + (u2.z + u3.z) - wa * xi.z;
        uu.w = (u0.w + u1.w) + (u2.w + u3.w) - wa * xi.w;
        float su2 = uu.x * uu.x + uu.y * uu.y + uu.z * uu.z + uu.w * uu.w;
        float sxu = xi.x * uu.x + xi.y * uu.y + xi.z * uu.z + xi.w * uu.w;
#pragma unroll
        for (int o = 16; o > 0; o >>= 1) {
            su2 += __shfl_xor_sync(FULLMASK, su2, o);
            sxu += __shfl_xor_sync(FULLMASK, sxu, o);
        }
        float un   = sqrtf(fmaxf(su2, 1e-15f));
        float coef = tanhf(un / omci) / un;     // tanh(lam*un/2)/un
        float xy   = coef * sxu;
        float y2   = coef * coef * su2;
        float den  = fmaxf(1.0f + 2.0f * xy + x2i * y2, 1e-15f);
        float An   = 1.0f + 2.0f * xy + y2;
        float Bn   = omi * coef;
        float inv  = 1.0f / den;
        float4 o;
        o.x = (An * xi.x + Bn * uu.x) * inv;
        o.y = (An * xi.y + Bn * uu.y) * inv;
        o.z = (An * xi.z + Bn * uu.z) * inv;
        o.w = (An * xi.w + Bn * uu.w) * inv;
        *(float4*)&out[i * DIM + 4 * lane] = o;
    }
}

// ---------------------------------------------------------------------------
extern "C" void kernel_launch(void* const* d_in, const int* in_sizes, int n_in,
                              void* d_out, int out_size) {
    const float* x    = (const float*)d_in[0];   // [1,1024,128]
    const float* adj  = (const float*)d_in[1];   // [1,1024,1024]
    const float* attw = (const float*)d_in[2];   // [256]
    const float* attb = (const float*)d_in[3];   // scalar
    float* out = (float*)d_out;                  // [1,1024,128]

    k_pre<<<128, 256>>>(x, attw, attb);
    k_fused<<<NPTS, 128>>>(x, adj, out);
}

// round 7
// speedup vs baseline: 1.2168x; 1.2168x over previous
#include <cuda_runtime.h>
#include <cstddef>

#define NPTS 1024
#define DIM  128
#define FULLMASK 0xffffffffu
#define CAP 256

__device__ __forceinline__ float warp_sum(float v) {
#pragma unroll
    for (int o = 16; o > 0; o >>= 1) v += __shfl_xor_sync(FULLMASK, v, o);
    return v;
}

// atanh(min(s,1-1e-7)) via fast log; s >= 0
__device__ __forceinline__ float fast_atanh(float s) {
    s = fminf(s, 1.0f - 1e-7f);
    return 0.5f * __logf(__fdividef(1.0f + s, 1.0f - s));
}

// ---------------------------------------------------------------------------
// Single fused kernel: block (128 threads, 4 warps) per row i.
//  step0: stage x_i, w1, w2; row scalars x2_i, E_i = exp(-(left_i+b))
//  step1: ballot-compact nonzero adj entries of row i
//  step1b: PER-NEIGHBOR stats pass (warp per neighbor, float4/lane covers
//          all of D): x2_j and F_j = exp(-right_j) into smem
//  step2: quad-per-pair dot (single FMA chain, interleaved 64B slices)
//         + scalar chain using smem per-neighbor scalars
//  step3: dim-per-lane coalesced aggregation u = sum wb_j x_j
//  step4: expmap epilogue on warp 0
// ---------------------------------------------------------------------------
__global__ void __launch_bounds__(128, 8) k_fused(
    const float* __restrict__ x, const float* __restrict__ adj,
    const float* __restrict__ attw, const float* __restrict__ attb,
    float* __restrict__ out)
{
    __shared__ __align__(16) float s_xi[DIM];
    __shared__ __align__(16) float s_w2[DIM];
    __shared__ int   s_idx[CAP];
    __shared__ float s_val[CAP];
    __shared__ float s_wb[CAP];
    __shared__ float s_x2j[CAP];
    __shared__ float s_F[CAP];
    __shared__ __align__(16) float s_u[4][DIM];
    __shared__ float s_red[12];
    __shared__ int   s_wcnt[4];

    const int i    = blockIdx.x;
    const int t    = threadIdx.x;          // 0..127
    const int warp = t >> 5, lane = t & 31;

    // ---- step 0: stage x_i, w2; row scalars ----
    float a = x[i * DIM + t];
    s_xi[t] = a;
    s_w2[t] = attw[DIM + t];
    float x2p = a * a;
    float d1p = a * attw[t];
    x2p = warp_sum(x2p); d1p = warp_sum(d1p);
    if (lane == 0) { s_red[warp] = x2p; s_red[4 + warp] = d1p; }
    __syncthreads();
    const float x2i = s_red[0] + s_red[1] + s_red[2] + s_red[3];
    const float d1  = s_red[4] + s_red[5] + s_red[6] + s_red[7];
    const float pni = sqrtf(fmaxf(x2i, 1e-15f));
    const float Ei  = __expf(-(fast_atanh(pni) / pni * d1 + attb[0]));
    const float omi  = 1.0f - x2i;
    const float omci = fmaxf(omi, 1e-15f);

    // ---- step 1: compaction (warp w scans 256 entries; vals re-read) ----
    const float* arow = adj + (size_t)i * NPTS + warp * 256;
    unsigned masks[8];
    int mycnt = 0;
#pragma unroll
    for (int c = 0; c < 8; c++) {
        float v = arow[c * 32 + lane];
        unsigned m = __ballot_sync(FULLMASK, v != 0.0f);
        masks[c] = m;
        mycnt += __popc(m);
    }
    if (lane == 0) s_wcnt[warp] = mycnt;
    __syncthreads();
    int run = 0;
#pragma unroll
    for (int w = 0; w < 4; w++) if (w < warp) run += s_wcnt[w];
#pragma unroll
    for (int c = 0; c < 8; c++) {
        unsigned m = masks[c];
        if (m & (1u << lane)) {
            int pos = run + __popc(m & ((1u << lane) - 1));
            if (pos < CAP) {
                s_idx[pos] = warp * 256 + c * 32 + lane;
                s_val[pos] = arow[c * 32 + lane];   // L1 hit
            }
        }
        run += __popc(m);
    }
    const int cnt = min(s_wcnt[0] + s_wcnt[1] + s_wcnt[2] + s_wcnt[3], CAP);
    __syncthreads();

    // ---- step 1b: per-neighbor stats (warp per neighbor) ----
    {
        float4 w2 = ((const float4*)s_w2)[lane];
        for (int k = warp; k < cnt; k += 4) {
            int j = s_idx[k];
            float4 b = *(const float4*)(x + j * DIM + 4 * lane);
            float x2j = b.x * b.x + b.y * b.y + b.z * b.z + b.w * b.w;
            float d2j = w2.x * b.x + w2.y * b.y + w2.z * b.z + w2.w * b.w;
            x2j = warp_sum(x2j); d2j = warp_sum(d2j);
            if (lane == 0) {
                float pnj = sqrtf(fmaxf(x2j, 1e-15f));
                s_x2j[k] = x2j;
                s_F[k]   = __expf(-(fast_atanh(pnj) / pnj * d2j));
            }
        }
    }
    __syncthreads();

    // ---- step 2: quad-per-pair dot + scalar chain (32 pairs per sweep) ----
    const int slice = lane & 3;
    float4 xir[8];
#pragma unroll
    for (int m = 0; m < 8; m++) xir[m] = ((const float4*)s_xi)[m * 4 + slice];

    float wa_lane = 0.0f;
    for (int kb = 0; kb < cnt; kb += 32) {
        int  k   = kb + warp * 8 + (lane >> 2);
        bool act = k < cnt;
        int  j   = act ? s_idx[k] : i;
        float av = act ? s_val[k] : 0.0f;
        const float4* xj4 = (const float4*)(x + j * DIM);
        float d = 0.f;
#pragma unroll
        for (int m = 0; m < 8; m++) {
            float4 b  = xj4[m * 4 + slice];            // quad covers 64B/m
            float4 aa = xir[m];
            d += aa.x * b.x + aa.y * b.y + aa.z * b.z + aa.w * b.w;
        }
        d += __shfl_xor_sync(FULLMASK, d, 1);
        d += __shfl_xor_sync(FULLMASK, d, 2);

        float x2j = act ? s_x2j[k] : x2i;
        float Fj  = act ? s_F[k]   : 1.0f;
        // attention: adj * sigmoid(left+right+b) = av / (1 + Ei*Fj)
        float sig = __fdividef(av, 1.0f + Ei * Fj);
        // pairwise logmap scalar chain
        float P   = 1.0f - 2.0f * d;
        float A   = P + x2j;                             // coeff of -x_i
        float den = fmaxf(P + x2i * x2j, 1e-15f);        // mobius denom
        float Q   = x2i * A * A - 2.0f * A * omi * d + x2j * omi * omi;
        Q = fmaxf(Q, 1e-15f * den * den);                // sn2 clamp * den^2
        float rq  = rsqrtf(Q);
        float sq  = Q * rq;                              // sqrt(Q)
        float dm  = fmaxf(den - sq, 1e-7f * den);        // atanh clip
        float ath = 0.5f * __logf(__fdividef(den + sq, dm));
        float wgt = sig * omci * ath * rq;
        if (slice == 0) {
            wa_lane += wgt * A;
            if (act) s_wb[k] = wgt * omi;
        }
    }
    wa_lane = warp_sum(wa_lane);
    if (lane == 0) s_red[8 + warp] = wa_lane;
    __syncthreads();

    // ---- step 3: dim-per-lane coalesced aggregation ----
    float4 u = {0.f, 0.f, 0.f, 0.f};
    for (int k = warp; k < cnt; k += 4) {
        float wb = s_wb[k];
        float4 b = *(const float4*)(x + s_idx[k] * DIM + 4 * lane);
        u.x += wb * b.x; u.y += wb * b.y; u.z += wb * b.z; u.w += wb * b.w;
    }
    ((float4*)s_u[warp])[lane] = u;
    __syncthreads();

    // ---- step 4: expmap epilogue (warp 0, float4 per lane covers D=128) ----
    if (warp == 0) {
        float4 u0 = ((const float4*)s_u[0])[lane];
        float4 u1 = ((const float4*)s_u[1])[lane];
        float4 u2 = ((const float4*)s_u[2])[lane];
        float4 u3 = ((const float4*)s_u[3])[lane];
        float  wa = s_red[8] + s_red[9] + s_red[10] + s_red[11];
        float4 xi = ((const float4*)s_xi)[lane];
        float4 uu;
        uu.x = (u0.x + u1.x) + (u2.x + u3.x) - wa * xi.x;
        uu.y = (u0.y + u1.y) + (u2.y + u3.y) - wa * xi.y;
        uu.z = (u0.z + u1.z) + (u2.z + u3.z) - wa * xi.z;
        uu.w = (u0.w + u1.w) + (u2.w + u3.w) - wa * xi.w;
        float su2 = uu.x * uu.x + uu.y * uu.y + uu.z * uu.z + uu.w * uu.w;
        float sxu = xi.x * uu.x + xi.y * uu.y + xi.z * uu.z + xi.w * uu.w;
#pragma unroll
        for (int o = 16; o > 0; o >>= 1) {
            su2 += __shfl_xor_sync(FULLMASK, su2, o);
            sxu += __shfl_xor_sync(FULLMASK, sxu, o);
        }
        float un   = sqrtf(fmaxf(su2, 1e-15f));
        float coef = tanhf(un / omci) / un;     // tanh(lam*un/2)/un
        float xy   = coef * sxu;
        float y2   = coef * coef * su2;
        float den  = fmaxf(1.0f + 2.0f * xy + x2i * y2, 1e-15f);
        float An   = 1.0f + 2.0f * xy + y2;
        float Bn   = omi * coef;
        float inv  = 1.0f / den;
        float4 o;
        o.x = (An * xi.x + Bn * uu.x) * inv;
        o.y = (An * xi.y + Bn * uu.y) * inv;
        o.z = (An * xi.z + Bn * uu.z) * inv;
        o.w = (An * xi.w + Bn * uu.w) * inv;
        *(float4*)&out[i * DIM + 4 * lane] = o;
    }
}

// ---------------------------------------------------------------------------
extern "C" void kernel_launch(void* const* d_in, const int* in_sizes, int n_in,
                              void* d_out, int out_size) {
    const float* x    = (const float*)d_in[0];   // [1,1024,128]
    const float* adj  = (const float*)d_in[1];   // [1,1024,1024]
    const float* attw = (const float*)d_in[2];   // [256]
    const float* attb = (const float*)d_in[3];   // scalar
    float* out = (float*)d_out;                  // [1,1024,128]

    k_fused<<<NPTS, 128>>>(x, adj, attw, attb, out);
}

// round 8
// speedup vs baseline: 1.5175x; 1.2471x over previous
#include <cuda_runtime.h>
#include <cstddef>

#define NPTS 1024
#define DIM  128
#define FULLMASK 0xffffffffu
#define CAP 256
#define NPROD 128            // producer blocks (must be <= SM count for wave-1 residency)

// ---- per-point scratch + sync counters (zero-initialized; reset each launch) ----
__device__ float g_x2[NPTS];
__device__ float g_F[NPTS];    // exp(-right_j)
__device__ int   g_done;       // producers finished
__device__ int   g_fin;        // blocks finished (for counter reset)

__device__ __forceinline__ float warp_sum(float v) {
#pragma unroll
    for (int o = 16; o > 0; o >>= 1) v += __shfl_xor_sync(FULLMASK, v, o);
    return v;
}

// atanh(min(s,1-1e-7)) via fast log; s >= 0
__device__ __forceinline__ float fast_atanh(float s) {
    s = fminf(s, 1.0f - 1e-7f);
    return 0.5f * __logf(__fdividef(1.0f + s, 1.0f - s));
}

// ---------------------------------------------------------------------------
// Single launch. Block (128 threads) per row i.
//  step0 : stage x_i; row scalars x2_i, E_i = exp(-(left_i+b))
//  prod  : blocks 0..127 compute g_x2/g_F for 8 points each, fence, count
//  step1 : ballot-compact nonzero adj entries of row i (overlap with prod)
//  spin  : wait g_done == NPROD
//  step2 : quad-per-pair dot (single FMA chain) + scalar chain w/ g_x2,g_F
//  step3 : dim-per-lane coalesced aggregation
//  step4 : expmap epilogue on warp 0
//  tail  : last block resets counters (graph-replay safe)
// ---------------------------------------------------------------------------
__global__ void __launch_bounds__(128, 8) k_fused(
    const float* __restrict__ x, const float* __restrict__ adj,
    const float* __restrict__ attw, const float* __restrict__ attb,
    float* __restrict__ out)
{
    __shared__ __align__(16) float s_xi[DIM];
    __shared__ int   s_idx[CAP];
    __shared__ float s_val[CAP];
    __shared__ float s_wb[CAP];
    __shared__ __align__(16) float s_u[4][DIM];
    __shared__ float s_red[12];
    __shared__ int   s_wcnt[4];

    const int i    = blockIdx.x;
    const int t    = threadIdx.x;          // 0..127
    const int warp = t >> 5, lane = t & 31;

    // ---- step 0: stage x_i; own-row scalars ----
    float a = x[i * DIM + t];
    s_xi[t] = a;
    float x2p = a * a;
    float d1p = a * attw[t];
    x2p = warp_sum(x2p); d1p = warp_sum(d1p);
    if (lane == 0) { s_red[warp] = x2p; s_red[4 + warp] = d1p; }
    __syncthreads();
    const float x2i = s_red[0] + s_red[1] + s_red[2] + s_red[3];
    const float d1  = s_red[4] + s_red[5] + s_red[6] + s_red[7];
    const float pni = sqrtf(fmaxf(x2i, 1e-15f));
    const float Ei  = __expf(-(fast_atanh(pni) / pni * d1 + attb[0]));
    const float omi  = 1.0f - x2i;
    const float omci = fmaxf(omi, 1e-15f);

    // ---- producer phase: blocks 0..127 compute per-point stats ----
    if (i < NPROD) {
        float4 w2 = *(const float4*)&attw[DIM + 4 * lane];
        int p = i * 8 + warp * 2;
#pragma unroll
        for (int s = 0; s < 2; s++) {
            float4 v = *(const float4*)&x[(p + s) * DIM + 4 * lane];
            float x2 = v.x * v.x + v.y * v.y + v.z * v.z + v.w * v.w;
            float d2 = w2.x * v.x + w2.y * v.y + w2.z * v.z + w2.w * v.w;
            x2 = warp_sum(x2); d2 = warp_sum(d2);
            if (lane == 0) {
                float pn = sqrtf(fmaxf(x2, 1e-15f));
                g_x2[p + s] = x2;
                g_F[p + s]  = __expf(-(fast_atanh(pn) / pn * d2));
            }
        }
        __syncthreads();                 // all 4 warps' stores issued
        if (t == 0) { __threadfence(); atomicAdd(&g_done, 1); }
    }

    // ---- step 1: compaction (warp w scans 256 entries; vals re-read) ----
    const float* arow = adj + (size_t)i * NPTS + warp * 256;
    unsigned masks[8];
    int mycnt = 0;
#pragma unroll
    for (int c = 0; c < 8; c++) {
        float v = arow[c * 32 + lane];
        unsigned m = __ballot_sync(FULLMASK, v != 0.0f);
        masks[c] = m;
        mycnt += __popc(m);
    }
    if (lane == 0) s_wcnt[warp] = mycnt;
    __syncthreads();
    int run = 0;
#pragma unroll
    for (int w = 0; w < 4; w++) if (w < warp) run += s_wcnt[w];
#pragma unroll
    for (int c = 0; c < 8; c++) {
        unsigned m = masks[c];
        if (m & (1u << lane)) {
            int pos = run + __popc(m & ((1u << lane) - 1));
            if (pos < CAP) {
                s_idx[pos] = warp * 256 + c * 32 + lane;
                s_val[pos] = arow[c * 32 + lane];   // L1 hit
            }
        }
        run += __popc(m);
    }
    const int cnt = min(s_wcnt[0] + s_wcnt[1] + s_wcnt[2] + s_wcnt[3], CAP);

    // ---- spin: wait for all producer stats ----
    if (t == 0) {
        while (atomicAdd(&g_done, 0) < NPROD) __nanosleep(64);
        __threadfence();
    }
    __syncthreads();

    // ---- step 2: quad-per-pair dot + scalar chain (32 pairs per sweep) ----
    const int slice = lane & 3;
    float4 xir[8];
#pragma unroll
    for (int m = 0; m < 8; m++) xir[m] = ((const float4*)s_xi)[m * 4 + slice];

    float wa_lane = 0.0f;
    for (int kb = 0; kb < cnt; kb += 32) {
        int  k   = kb + warp * 8 + (lane >> 2);
        bool act = k < cnt;
        int  j   = act ? s_idx[k] : i;
        float av = act ? s_val[k] : 0.0f;
        const float4* xj4 = (const float4*)(x + j * DIM);
        float d = 0.f;
#pragma unroll
        for (int m = 0; m < 8; m++) {
            float4 b  = xj4[m * 4 + slice];            // quad covers 64B/m
            float4 aa = xir[m];
            d += aa.x * b.x + aa.y * b.y + aa.z * b.z + aa.w * b.w;
        }
        d += __shfl_xor_sync(FULLMASK, d, 1);
        d += __shfl_xor_sync(FULLMASK, d, 2);

        float x2j = act ? g_x2[j] : x2i;
        float Fj  = act ? g_F[j]  : 1.0f;
        // attention: adj * sigmoid(left+right+b) = av / (1 + Ei*Fj)
        float sig = __fdividef(av, 1.0f + Ei * Fj);
        // pairwise logmap scalar chain
        float P   = 1.0f - 2.0f * d;
        float A   = P + x2j;                             // coeff of -x_i
        float den = fmaxf(P + x2i * x2j, 1e-15f);        // mobius denom
        float Q   = x2i * A * A - 2.0f * A * omi * d + x2j * omi * omi;
        Q = fmaxf(Q, 1e-15f * den * den);                // sn2 clamp * den^2
        float rq  = rsqrtf(Q);
        float sq  = Q * rq;                              // sqrt(Q)
        float dm  = fmaxf(den - sq, 1e-7f * den);        // atanh clip
        float ath = 0.5f * __logf(__fdividef(den + sq, dm));
        float wgt = sig * omci * ath * rq;
        if (slice == 0) {
            wa_lane += wgt * A;
            if (act) s_wb[k] = wgt * omi;
        }
    }
    wa_lane = warp_sum(wa_lane);
    if (lane == 0) s_red[8 + warp] = wa_lane;
    __syncthreads();

    // ---- step 3: dim-per-lane coalesced aggregation ----
    float4 u = {0.f, 0.f, 0.f, 0.f};
    for (int k = warp; k < cnt; k += 4) {
        float wb = s_wb[k];
        float4 b = *(const float4*)(x + s_idx[k] * DIM + 4 * lane);
        u.x += wb * b.x; u.y += wb * b.y; u.z += wb * b.z; u.w += wb * b.w;
    }
    ((float4*)s_u[warp])[lane] = u;
    __syncthreads();

    // ---- step 4: expmap epilogue (warp 0, float4 per lane covers D=128) ----
    if (warp == 0) {
        float4 u0 = ((const float4*)s_u[0])[lane];
        float4 u1 = ((const float4*)s_u[1])[lane];
        float4 u2 = ((const float4*)s_u[2])[lane];
        float4 u3 = ((const float4*)s_u[3])[lane];
        float  wa = s_red[8] + s_red[9] + s_red[10] + s_red[11];
        float4 xi = ((const float4*)s_xi)[lane];
        float4 uu;
        uu.x = (u0.x + u1.x) + (u2.x + u3.x) - wa * xi.x;
        uu.y = (u0.y + u1.y) + (u2.y + u3.y) - wa * xi.y;
        uu.z = (u0.z + u1.z) + (u2.z + u3.z) - wa * xi.z;
        uu.w = (u0.w + u1.w) + (u2.w + u3.w) - wa * xi.w;
        float su2 = uu.x * uu.x + uu.y * uu.y + uu.z * uu.z + uu.w * uu.w;
        float sxu = xi.x * uu.x + xi.y * uu.y + xi.z * uu.z + xi.w * uu.w;
#pragma unroll
        for (int o = 16; o > 0; o >>= 1) {
            su2 += __shfl_xor_sync(FULLMASK, su2, o);
            sxu += __shfl_xor_sync(FULLMASK, sxu, o);
        }
        float un   = sqrtf(fmaxf(su2, 1e-15f));
        float coef = tanhf(un / omci) / un;     // tanh(lam*un/2)/un
        float xy   = coef * sxu;
        float y2   = coef * coef * su2;
        float den  = fmaxf(1.0f + 2.0f * xy + x2i * y2, 1e-15f);
        float An   = 1.0f + 2.0f * xy + y2;
        float Bn   = omi * coef;
        float inv  = 1.0f / den;
        float4 o;
        o.x = (An * xi.x + Bn * uu.x) * inv;
        o.y = (An * xi.y + Bn * uu.y) * inv;
        o.z = (An * xi.z + Bn * uu.z) * inv;
        o.w = (An * xi.w + Bn * uu.w) * inv;
        *(float4*)&out[i * DIM + 4 * lane] = o;
    }

    // ---- tail: last block to finish resets the counters (replay-safe) ----
    if (t == 0) {
        __threadfence();
        int f = atomicAdd(&g_fin, 1);
        if (f == (int)gridDim.x - 1) { g_done = 0; g_fin = 0; }
    }
}

// ---------------------------------------------------------------------------
extern "C" void kernel_launch(void* const* d_in, const int* in_sizes, int n_in,
                              void* d_out, int out_size) {
    const float* x    = (const float*)d_in[0];   // [1,1024,128]
    const float* adj  = (const float*)d_in[1];   // [1,1024,1024]
    const float* attw = (const float*)d_in[2];   // [256]
    const float* attb = (const float*)d_in[3];   // scalar
    float* out = (float*)d_out;                  // [1,1024,128]

    k_fused<<<NPTS, 128>>>(x, adj, attw, attb, out);
}

// round 9
// speedup vs baseline: 1.6561x; 1.0913x over previous
#include <cuda_runtime.h>
#include <cstddef>

#define NPTS 1024
#define DIM  128
#define FULLMASK 0xffffffffu
#define CAP 256

// ---- per-point scratch + sync counters (zero-init; reset at end of launch) ----
__device__ float2 g_stat[NPTS];   // (x2_j, F_j = exp(-right_j))
__device__ int    g_done;         // blocks that published their point stats
__device__ int    g_fin;          // blocks finished (for counter reset)

__device__ __forceinline__ float warp_sum(float v) {
#pragma unroll
    for (int o = 16; o > 0; o >>= 1) v += __shfl_xor_sync(FULLMASK, v, o);
    return v;
}

// atanh(min(s,1-1e-7)) via fast log; s >= 0
__device__ __forceinline__ float fast_atanh(float s) {
    s = fminf(s, 1.0f - 1e-7f);
    return 0.5f * __logf(__fdividef(1.0f + s, 1.0f - s));
}

// ---------------------------------------------------------------------------
// Single launch, all-blocks-produce scheme. Block (128 threads) per row i.
//  step0 : stage x_i; reduce x2_i, d1, d2 together (ILP); thread 0 publishes
//          g_stat[i] = (x2_i, exp(-right_i)) and arrives on g_done
//  step1 : ballot-compact nonzero adj entries of row i (hides stats latency)
//  spin  : wait g_done == gridDim (all 1024 blocks wave-1 resident)
//  step2 : quad-per-pair dot (single FMA chain) + scalar chain w/ g_stat
//  step3 : dim-per-lane coalesced aggregation
//  step4 : expmap epilogue on warp 0
//  tail  : last block resets counters (graph-replay safe)
// ---------------------------------------------------------------------------
__global__ void __launch_bounds__(128, 8) k_fused(
    const float* __restrict__ x, const float* __restrict__ adj,
    const float* __restrict__ attw, const float* __restrict__ attb,
    float* __restrict__ out)
{
    __shared__ __align__(16) float s_xi[DIM];
    __shared__ int   s_idx[CAP];
    __shared__ float s_val[CAP];
    __shared__ float s_wb[CAP];
    __shared__ __align__(16) float s_u[4][DIM];
    __shared__ float s_red[16];
    __shared__ int   s_wcnt[4];

    const int i    = blockIdx.x;
    const int t    = threadIdx.x;          // 0..127
    const int warp = t >> 5, lane = t & 31;

    // ---- step 0: stage x_i; reduce x2, d1, d2 with full ILP ----
    float a = x[i * DIM + t];
    s_xi[t] = a;
    float x2p = a * a;
    float d1p = a * attw[t];
    float d2p = a * attw[DIM + t];
#pragma unroll
    for (int o = 16; o > 0; o >>= 1) {
        x2p += __shfl_xor_sync(FULLMASK, x2p, o);
        d1p += __shfl_xor_sync(FULLMASK, d1p, o);
        d2p += __shfl_xor_sync(FULLMASK, d2p, o);
    }
    if (lane == 0) { s_red[warp] = x2p; s_red[4 + warp] = d1p; s_red[8 + warp] = d2p; }
    __syncthreads();
    const float x2i = s_red[0] + s_red[1] + s_red[2] + s_red[3];
    const float d1  = s_red[4] + s_red[5] + s_red[6] + s_red[7];
    const float pni = sqrtf(fmaxf(x2i, 1e-15f));
    const float fac = fast_atanh(pni) / pni;
    const float Ei  = __expf(-(fac * d1 + attb[0]));
    const float omi  = 1.0f - x2i;
    const float omci = fmaxf(omi, 1e-15f);
    if (t == 0) {
        float d2 = s_red[8] + s_red[9] + s_red[10] + s_red[11];
        g_stat[i] = make_float2(x2i, __expf(-(fac * d2)));
        __threadfence();
        atomicAdd(&g_done, 1);
    }

    // ---- step 1: compaction (warp w scans 256 entries; vals re-read) ----
    const float* arow = adj + (size_t)i * NPTS + warp * 256;
    unsigned masks[8];
    int mycnt = 0;
#pragma unroll
    for (int c = 0; c < 8; c++) {
        float v = arow[c * 32 + lane];
        unsigned m = __ballot_sync(FULLMASK, v != 0.0f);
        masks[c] = m;
        mycnt += __popc(m);
    }
    if (lane == 0) s_wcnt[warp] = mycnt;
    __syncthreads();
    int run = 0;
#pragma unroll
    for (int w = 0; w < 4; w++) if (w < warp) run += s_wcnt[w];
#pragma unroll
    for (int c = 0; c < 8; c++) {
        unsigned m = masks[c];
        if (m & (1u << lane)) {
            int pos = run + __popc(m & ((1u << lane) - 1));
            if (pos < CAP) {
                s_idx[pos] = warp * 256 + c * 32 + lane;
                s_val[pos] = arow[c * 32 + lane];   // L1 hit
            }
        }
        run += __popc(m);
    }
    const int cnt = min(s_wcnt[0] + s_wcnt[1] + s_wcnt[2] + s_wcnt[3], CAP);

    // ---- spin: wait for every block's point stats (all wave-1 resident) ----
    if (t == 0) {
        while (*(volatile int*)&g_done < (int)gridDim.x) __nanosleep(32);
        __threadfence();
    }
    __syncthreads();

    // ---- step 2: quad-per-pair dot + scalar chain (32 pairs per sweep) ----
    const int slice = lane & 3;
    float4 xir[8];
#pragma unroll
    for (int m = 0; m < 8; m++) xir[m] = ((const float4*)s_xi)[m * 4 + slice];

    float wa_lane = 0.0f;
    for (int kb = 0; kb < cnt; kb += 32) {
        int  k   = kb + warp * 8 + (lane >> 2);
        bool act = k < cnt;
        int  j   = act ? s_idx[k] : i;
        float av = act ? s_val[k] : 0.0f;
        const float4* xj4 = (const float4*)(x + j * DIM);
        float d = 0.f;
#pragma unroll
        for (int m = 0; m < 8; m++) {
            float4 b  = xj4[m * 4 + slice];            // quad covers 64B/m
            float4 aa = xir[m];
            d += aa.x * b.x + aa.y * b.y + aa.z * b.z + aa.w * b.w;
        }
        d += __shfl_xor_sync(FULLMASK, d, 1);
        d += __shfl_xor_sync(FULLMASK, d, 2);

        float2 st = g_stat[j];
        float x2j = st.x;
        // attention: adj * sigmoid(left+right+b) = av / (1 + Ei*Fj)
        float sig = __fdividef(av, 1.0f + Ei * st.y);
        // pairwise logmap scalar chain
        float P   = 1.0f - 2.0f * d;
        float A   = P + x2j;                             // coeff of -x_i
        float den = fmaxf(P + x2i * x2j, 1e-15f);        // mobius denom
        float Q   = x2i * A * A - 2.0f * A * omi * d + x2j * omi * omi;
        Q = fmaxf(Q, 1e-15f * den * den);                // sn2 clamp * den^2
        float rq  = rsqrtf(Q);
        float sq  = Q * rq;                              // sqrt(Q)
        float dm  = fmaxf(den - sq, 1e-7f * den);        // atanh clip
        float ath = 0.5f * __logf(__fdividef(den + sq, dm));
        float wgt = sig * omci * ath * rq;
        if (slice == 0) {
            wa_lane += wgt * A;
            if (act) s_wb[k] = wgt * omi;
        }
    }
    wa_lane = warp_sum(wa_lane);
    if (lane == 0) s_red[12 + warp] = wa_lane;
    __syncthreads();

    // ---- step 3: dim-per-lane coalesced aggregation ----
    float4 u = {0.f, 0.f, 0.f, 0.f};
    for (int k = warp; k < cnt; k += 4) {
        float wb = s_wb[k];
        float4 b = *(const float4*)(x + s_idx[k] * DIM + 4 * lane);
        u.x += wb * b.x; u.y += wb * b.y; u.z += wb * b.z; u.w += wb * b.w;
    }
    ((float4*)s_u[warp])[lane] = u;
    __syncthreads();

    // ---- step 4: expmap epilogue (warp 0, float4 per lane covers D=128) ----
    if (warp == 0) {
        float4 u0 = ((const float4*)s_u[0])[lane];
        float4 u1 = ((const float4*)s_u[1])[lane];
        float4 u2 = ((const float4*)s_u[2])[lane];
        float4 u3 = ((const float4*)s_u[3])[lane];
        float  wa = s_red[12] + s_red[13] + s_red[14] + s_red[15];
        float4 xi = ((const float4*)s_xi)[lane];
        float4 uu;
        uu.x = (u0.x + u1.x) + (u2.x + u3.x) - wa * xi.x;
        uu.y = (u0.y + u1.y) + (u2.y + u3.y) - wa * xi.y;
        uu.z = (u0.z + u1.z) + (u2.z + u3.z) - wa * xi.z;
        uu.w = (u0.w + u1.w) + (u2.w + u3.w) - wa * xi.w;
        float su2 = uu.x * uu.x + uu.y * uu.y + uu.z * uu.z + uu.w * uu.w;
        float sxu = xi.x * uu.x + xi.y * uu.y + xi.z * uu.z + xi.w * uu.w;
#pragma unroll
        for (int o = 16; o > 0; o >>= 1) {
            su2 += __shfl_xor_sync(FULLMASK, su2, o);
            sxu += __shfl_xor_sync(FULLMASK, sxu, o);
        }
        float un   = sqrtf(fmaxf(su2, 1e-15f));
        float coef = tanhf(un / omci) / un;     // tanh(lam*un/2)/un
        float xy   = coef * sxu;
        float y2   = coef * coef * su2;
        float den  = fmaxf(1.0f + 2.0f * xy + x2i * y2, 1e-15f);
        float An   = 1.0f + 2.0f * xy + y2;
        float Bn   = omi * coef;
        float inv  = 1.0f / den;
        float4 o;
        o.x = (An * xi.x + Bn * uu.x) * inv;
        o.y = (An * xi.y + Bn * uu.y) * inv;
        o.z = (An * xi.z + Bn * uu.z) * inv;
        o.w = (An * xi.w + Bn * uu.w) * inv;
        *(float4*)&out[i * DIM + 4 * lane] = o;
    }

    // ---- tail: last block to finish resets the counters (replay-safe) ----
    if (t == 0) {
        __threadfence();
        int f = atomicAdd(&g_fin, 1);
        if (f == (int)gridDim.x - 1) { g_done = 0; g_fin = 0; }
    }
}

// ---------------------------------------------------------------------------
extern "C" void kernel_launch(void* const* d_in, const int* in_sizes, int n_in,
                              void* d_out, int out_size) {
    const float* x    = (const float*)d_in[0];   // [1,1024,128]
    const float* adj  = (const float*)d_in[1];   // [1,1024,1024]
    const float* attw = (const float*)d_in[2];   // [256]
    const float* attb = (const float*)d_in[3];   // scalar
    float* out = (float*)d_out;                  // [1,1024,128]

    k_fused<<<NPTS, 128>>>(x, adj, attw, attb, out);
}